// round 15
// baseline (speedup 1.0000x reference)
#include <cuda_runtime.h>
#include <cuda_bf16.h>
#include <math.h>

#define NQ 1024
#define MI_STRIDE 544

// ---------------- scratch (device globals; no allocation) ----------------
__device__ float g_cv[NQ * 4096];
__device__ float g_pos[NQ * 2];
__device__ float g_occv[NQ];
__device__ float g_expd[NQ];
__device__ float g_feats[NQ * 384];
__device__ float g_fgavg[32 * 32 * 256];
__device__ __nv_bfloat16 g_mlpinh[NQ * MI_STRIDE];
__device__ __nv_bfloat16 g_hidh[NQ * 512];
__device__ __nv_bfloat16 g_miwh[512 * 544];
__device__ __nv_bfloat16 g_mowh[448 * 512];

__device__ __forceinline__ float gelu_tanh(float x) {
    float x3 = x * x * x;
    return 0.5f * x * (1.f + tanhf(0.7978845608028654f * (x + 0.044715f * x3)));
}

__device__ __forceinline__ float tf32r(float x) {
    unsigned u;
    asm("cvt.rna.tf32.f32 %0, %1;" : "=r"(u) : "f"(x));
    return __uint_as_float(u);
}

__device__ __forceinline__ unsigned packbf(float lo, float hi) {
    __nv_bfloat162 v = __floats2bfloat162_rn(lo, hi);
    return *(unsigned*)&v;
}

__device__ __forceinline__ void mma_tf32(float& d0, float& d1, float& d2, float& d3,
                                         float a0, float a1, float a2, float a3,
                                         float b0, float b1) {
    asm("mma.sync.aligned.m16n8k8.row.col.f32.tf32.tf32.f32 "
        "{%0,%1,%2,%3},{%4,%5,%6,%7},{%8,%9},{%0,%1,%2,%3};"
        : "+f"(d0), "+f"(d1), "+f"(d2), "+f"(d3)
        : "r"(__float_as_uint(a0)), "r"(__float_as_uint(a1)),
          "r"(__float_as_uint(a2)), "r"(__float_as_uint(a3)),
          "r"(__float_as_uint(b0)), "r"(__float_as_uint(b1)));
}

__device__ __forceinline__ void mma_bf16(float& d0, float& d1, float& d2, float& d3,
                                         unsigned a0, unsigned a1, unsigned a2, unsigned a3,
                                         unsigned b0, unsigned b1) {
    asm("mma.sync.aligned.m16n8k16.row.col.f32.bf16.bf16.f32 "
        "{%0,%1,%2,%3},{%4,%5,%6,%7},{%8,%9},{%0,%1,%2,%3};"
        : "+f"(d0), "+f"(d1), "+f"(d2), "+f"(d3)
        : "r"(a0), "r"(a1), "r"(a2), "r"(a3), "r"(b0), "r"(b1));
}

// ---------------- one-time weight convert+transpose ----------------
__global__ void k_prep(const float* __restrict__ miw, const float* __restrict__ mow) {
    int n = blockIdx.x, t = threadIdx.x;
    if (n < 512) {
        for (int k = t; k < 544; k += 256)
            g_miwh[n * 544 + k] = __float2bfloat16(k < 535 ? miw[k * 512 + n] : 0.f);
    } else {
        int nn = n - 512;
        for (int k = t; k < 512; k += 256)
            g_mowh[nn * 512 + k] = __float2bfloat16(nn < 388 ? mow[k * 388 + nn] : 0.f);
    }
}

// ---------------- cv = qf @ fg^T (tf32 mma) ----------------
__global__ __launch_bounds__(256) void k_cv(const float* __restrict__ A,
                                            const float* __restrict__ B,
                                            float* __restrict__ C) {
    __shared__ float As[64 * 17];
    __shared__ float Bs[16 * 73];
    int n0 = blockIdx.x * 64, m0 = blockIdx.y * 64, t = threadIdx.x;
    int w = t >> 5, lane = t & 31, qd = lane & 3, g = lane >> 2;
    int wm = (w >> 2) * 32, wn = (w & 3) * 16;
    int mm = t >> 2, k4 = (t & 3) * 4;
    float acc[2][2][4];
#pragma unroll
    for (int mt = 0; mt < 2; mt++)
#pragma unroll
        for (int nt = 0; nt < 2; nt++)
#pragma unroll
            for (int u = 0; u < 4; u++) acc[mt][nt][u] = 0.f;

    for (int k0 = 0; k0 < 256; k0 += 16) {
        float4 va = *(const float4*)&A[(m0 + mm) * 256 + k0 + k4];
        As[mm * 17 + k4 + 0] = tf32r(va.x);
        As[mm * 17 + k4 + 1] = tf32r(va.y);
        As[mm * 17 + k4 + 2] = tf32r(va.z);
        As[mm * 17 + k4 + 3] = tf32r(va.w);
        float4 vb = *(const float4*)&B[(n0 + mm) * 256 + k0 + k4];
        Bs[(k4 + 0) * 73 + mm] = tf32r(vb.x);
        Bs[(k4 + 1) * 73 + mm] = tf32r(vb.y);
        Bs[(k4 + 2) * 73 + mm] = tf32r(vb.z);
        Bs[(k4 + 3) * 73 + mm] = tf32r(vb.w);
        __syncthreads();
#pragma unroll
        for (int s = 0; s < 2; s++) {
            float a[2][4], b[2][2];
#pragma unroll
            for (int mt = 0; mt < 2; mt++) {
                int row = wm + mt * 16 + g;
                a[mt][0] = As[row * 17 + s * 8 + qd];
                a[mt][1] = As[(row + 8) * 17 + s * 8 + qd];
                a[mt][2] = As[row * 17 + s * 8 + qd + 4];
                a[mt][3] = As[(row + 8) * 17 + s * 8 + qd + 4];
            }
#pragma unroll
            for (int nt = 0; nt < 2; nt++) {
                int bn = wn + nt * 8 + g;
                b[nt][0] = Bs[(s * 8 + qd) * 73 + bn];
                b[nt][1] = Bs[(s * 8 + qd + 4) * 73 + bn];
            }
#pragma unroll
            for (int mt = 0; mt < 2; mt++)
#pragma unroll
                for (int nt = 0; nt < 2; nt++)
                    mma_tf32(acc[mt][nt][0], acc[mt][nt][1], acc[mt][nt][2], acc[mt][nt][3],
                             a[mt][0], a[mt][1], a[mt][2], a[mt][3], b[nt][0], b[nt][1]);
        }
        __syncthreads();
    }
#pragma unroll
    for (int mt = 0; mt < 2; mt++)
#pragma unroll
        for (int nt = 0; nt < 2; nt++) {
            int mg = m0 + wm + mt * 16 + g;
            int ng = n0 + wn + nt * 8 + qd * 2;
            *(float2*)&C[mg * 4096 + ng] = make_float2(acc[mt][nt][0], acc[mt][nt][1]);
            *(float2*)&C[(mg + 8) * 4096 + ng] = make_float2(acc[mt][nt][2], acc[mt][nt][3]);
        }
}

// ---------------- fg_avg (2x2 mean pool) ----------------
__global__ void k_fgavg(const float* __restrict__ fg, float* __restrict__ out) {
    int b = blockIdx.x;
    int y = b >> 5, x = b & 31, t = threadIdx.x;
    const float* p = fg + ((2 * y) * 64 + 2 * x) * 256;
    float v = p[t] + p[256 + t] + p[64 * 256 + t] + p[64 * 256 + 256 + t];
    out[(y * 32 + x) * 256 + t] = 0.25f * v;
}

// ---------------- per-query head (CV_S 68, OC_S 68, data col offset 1) ----------------
#define CV_S 68
#define OC_S 68
__global__ __launch_bounds__(256, 3) void k_head(
    const float* __restrict__ cv_g, const float* __restrict__ hq, const float* __restrict__ qf,
    const float* __restrict__ w1, const float* __restrict__ b1,
    const float* __restrict__ w2, const float* __restrict__ b2,
    const float* __restrict__ w3, const float* __restrict__ b3,
    const float* __restrict__ w4, const float* __restrict__ b4,
    const float* __restrict__ occw, const float* __restrict__ occb) {
    extern __shared__ float sm[];
    float* s_cv   = sm;                       // 66*68 = 4488
    float* s_occ  = s_cv + 4488;              // 160*68 = 10880
    unsigned* s_w3b = (unsigned*)(s_occ + 10880); // 72*33 = 2376
    float* s_ko   = (float*)(s_w3b + 2376);   // 144
    float* s_w2   = s_ko + 144;               // 192
    float* s_w4   = s_w2 + 192;               // 512
    float* s_b3   = s_w4 + 512;               // 32
    float* s_b4   = s_b3 + 32;                // 16
    float* s_ow   = s_b4 + 16;                // 32
    float* s_ob   = s_ow + 32;                // 2
    float* s_red  = s_ob + 2;                 // 32
    float* s_o3   = s_red + 32;               // 32
    float* s_h4   = s_o3 + 32;                // 16
    int* s_koi = (int*)s_ko;

    int q = blockIdx.x, t = threadIdx.x;
    const float* cvq = cv_g + q * 4096;
    for (int i = t; i < 4096; i += 256) s_cv[(1 + (i >> 6)) * CV_S + 1 + (i & 63)] = cvq[i];
    if (t < 68) { s_cv[t] = 0.f; s_cv[65 * CV_S + t] = 0.f; }
    if (t < 64) {
        s_cv[(t + 1) * CV_S] = 0.f;
        s_cv[(t + 1) * CV_S + 65] = 0.f;
        s_cv[(t + 1) * CV_S + 66] = 0.f;
    }
    for (int i = t; i < 160; i += 256) {
        float* rb = &s_occ[i * OC_S];
        rb[0] = 0.f; rb[65] = 0.f; rb[66] = 0.f; rb[67] = 0.f;
    }
    for (int i = t; i < 144; i += 256) { int c = i / 9, k = i - c * 9; s_w2[c * 12 + k] = w2[i]; }
    for (int i = t; i < 72 * 32; i += 256) {
        int krow = i >> 5, oc = i & 31;
        int k = krow * 2;
        s_w3b[krow * 33 + oc] = packbf(w3[oc * 144 + k], w3[oc * 144 + k + 1]);
    }
    for (int i = t; i < 144; i += 256) {
        int ic = i / 9, rk = i - ic * 9;
        int dy = rk / 3, dx = rk - dy * 3;
        s_koi[i] = (dy * 16 + ic) * OC_S + dx;
    }
    for (int i = t; i < 512; i += 256) s_w4[i] = w4[i];
    if (t < 32) s_b3[t] = b3[t];
    if (t < 16) s_b4[t] = b4[t];
    if (t < 32) s_ow[t] = occw[t];
    if (t < 2)  s_ob[t] = occb[t];
    if (t < 32) s_o3[t] = 0.f;
    for (int i = t; i < 128; i += 256) g_feats[q * 384 + i] = hq[q * 128 + i];
    for (int i = t; i < 256; i += 256) g_feats[q * 384 + 128 + i] = qf[q * 256 + i];
    float b2v = b2[0];

    int c1 = t & 15, xg = (t >> 4) & 7, sl2 = t >> 7;
    int x0 = xg * 8;
    float w1r[9], b1r = b1[c1];
#pragma unroll
    for (int k = 0; k < 9; k++) w1r[k] = w1[c1 * 9 + k];

    // conv2 mapping: all 256 threads; warp = row rr2 = t>>5, lane pair of cols 2*(t&31)
    int rr2 = t >> 5, cc2 = t & 31;
    float pm[16];   // [band][2 cols]

    int wrp = t >> 5, lane = t & 31, qd = lane & 3, g = lane >> 2;
    int jrow3 = wrp >> 1;
    int col0 = (wrp & 1) * 16 + g;
    int base0 = (2 * jrow3 + 1) * (16 * OC_S) + 2 * col0 + 1;
    float macc[4][2];
#pragma unroll
    for (int nt = 0; nt < 4; nt++) { macc[nt][0] = 0.f; macc[nt][1] = 0.f; }

    __syncthreads();

    float b3n[4][2];
#pragma unroll
    for (int nt = 0; nt < 4; nt++) {
        b3n[nt][0] = s_b3[nt * 8 + qd * 2 + 0];
        b3n[nt][1] = s_b3[nt * 8 + qd * 2 + 1];
    }

    for (int r0 = 0; r0 < 64; r0 += 8) {
        int band = r0 >> 3;
#pragma unroll
        for (int s = 0; s < 5; s++) {
            int slot = sl2 + 2 * s;
            int row = r0 - 1 + slot;
            float* dst = &s_occ[(slot * 16 + c1) * OC_S + 1 + x0];
            if (row < 0 || row > 63) {
#pragma unroll
                for (int j = 0; j < 8; j++) dst[j] = 0.f;
                continue;
            }
            float xv[3][10];
#pragma unroll
            for (int dy = 0; dy < 3; dy++) {
                const float* rp = &s_cv[(row + dy) * CV_S + x0];
                float4 vA = *(const float4*)rp;
                float4 vB = *(const float4*)(rp + 4);
                float2 vC = *(const float2*)(rp + 8);
                xv[dy][0] = vA.x; xv[dy][1] = vA.y; xv[dy][2] = vA.z; xv[dy][3] = vA.w;
                xv[dy][4] = vB.x; xv[dy][5] = vB.y; xv[dy][6] = vB.z; xv[dy][7] = vB.w;
                xv[dy][8] = vC.x; xv[dy][9] = vC.y;
            }
#pragma unroll
            for (int j = 0; j < 8; j++) {
                float a = b1r;
#pragma unroll
                for (int dy = 0; dy < 3; dy++)
#pragma unroll
                    for (int dx = 0; dx < 3; dx++)
                        a = fmaf(w1r[dy * 3 + dx], xv[dy][j + dx], a);
                dst[j] = fmaxf(a, 0.f);
            }
        }
        __syncthreads();

        // ---- conv2 : all 256 threads, row r0+rr2, cols 2cc2, 2cc2+1 ----
        {
            float a0 = b2v, a1 = b2v;
#pragma unroll
            for (int c = 0; c < 16; c++) {
                float4 wA = *(const float4*)&s_w2[c * 12];
                float4 wB = *(const float4*)&s_w2[c * 12 + 4];
                float w8 = s_w2[c * 12 + 8];
                float wv[9] = {wA.x, wA.y, wA.z, wA.w, wB.x, wB.y, wB.z, wB.w, w8};
#pragma unroll
                for (int dy = 0; dy < 3; dy++) {
                    // abs cols 2cc2 .. 2cc2+3 (logical x-1 .. x+2 for x=2cc2)
                    const float* rp = &s_occ[((rr2 + dy) * 16 + c) * OC_S + 2 * cc2];
                    float2 vA = *(const float2*)rp;
                    float2 vB = *(const float2*)(rp + 2);
                    a0 = fmaf(wv[dy * 3 + 0], vA.x,
                         fmaf(wv[dy * 3 + 1], vA.y,
                         fmaf(wv[dy * 3 + 2], vB.x, a0)));
                    a1 = fmaf(wv[dy * 3 + 0], vA.y,
                         fmaf(wv[dy * 3 + 1], vB.x,
                         fmaf(wv[dy * 3 + 2], vB.y, a1)));
                }
            }
            pm[band * 2 + 0] = a0;
            pm[band * 2 + 1] = a1;
        }

        // ---- conv3 via bf16 mma (k16): 9 steps ----
        {
            float d[4][4];
#pragma unroll
            for (int nt = 0; nt < 4; nt++)
#pragma unroll
                for (int u = 0; u < 4; u++) d[nt][u] = 0.f;

#pragma unroll
            for (int st = 0; st < 9; st++) {
                int kE = st * 16 + 2 * qd;
                int kO = kE + 8;
                int e0 = s_koi[kE], e1 = s_koi[kE + 1];
                int o0 = s_koi[kO], o1 = s_koi[kO + 1];
                unsigned a0 = packbf(s_occ[base0 + e0],      s_occ[base0 + e1]);
                unsigned a1 = packbf(s_occ[base0 + 16 + e0], s_occ[base0 + 16 + e1]);
                unsigned a2 = packbf(s_occ[base0 + o0],      s_occ[base0 + o1]);
                unsigned a3 = packbf(s_occ[base0 + 16 + o0], s_occ[base0 + 16 + o1]);
                int kr = st * 8 + qd;
                const unsigned* bp0 = &s_w3b[kr * 33];
                const unsigned* bp1 = &s_w3b[(kr + 4) * 33];
#pragma unroll
                for (int nt = 0; nt < 4; nt++) {
                    unsigned b0 = bp0[nt * 8 + g];
                    unsigned b1 = bp1[nt * 8 + g];
                    mma_bf16(d[nt][0], d[nt][1], d[nt][2], d[nt][3], a0, a1, a2, a3, b0, b1);
                }
            }
#pragma unroll
            for (int nt = 0; nt < 4; nt++) {
                macc[nt][0] += fmaxf(d[nt][0] + b3n[nt][0], 0.f) + fmaxf(d[nt][2] + b3n[nt][0], 0.f);
                macc[nt][1] += fmaxf(d[nt][1] + b3n[nt][1], 0.f) + fmaxf(d[nt][3] + b3n[nt][1], 0.f);
            }
        }
        __syncthreads();
    }

#pragma unroll
    for (int nt = 0; nt < 4; nt++) {
#pragma unroll
        for (int j = 0; j < 2; j++) {
            float v = macc[nt][j];
#pragma unroll
            for (int o = 4; o <= 16; o <<= 1) v += __shfl_xor_sync(0xffffffffu, v, o);
            if (g == 0) atomicAdd(&s_o3[nt * 8 + qd * 2 + j], v);
        }
    }

    // softmax over pm (registers): row = 8*band + rr2, cols 2*cc2 + j
    float lmax = pm[0];
#pragma unroll
    for (int u = 1; u < 16; u++) lmax = fmaxf(lmax, pm[u]);
#pragma unroll
    for (int o = 16; o; o >>= 1) lmax = fmaxf(lmax, __shfl_xor_sync(0xffffffffu, lmax, o));
    if ((t & 31) == 0) s_red[t >> 5] = lmax;
    __syncthreads();
    if (t == 0) {
        float m = s_red[0];
        for (int i = 1; i < 8; i++) m = fmaxf(m, s_red[i]);
        s_red[31] = m;
    }
    __syncthreads();
    float m = s_red[31];
    float se = 0.f, sy = 0.f, sx = 0.f;
#pragma unroll
    for (int b = 0; b < 8; b++) {
        float rowf = (float)(8 * b + rr2);
#pragma unroll
        for (int j = 0; j < 2; j++) {
            float e = __expf((pm[b * 2 + j] - m) * 20.f);
            se += e;
            sy = fmaf(e, rowf, sy);
            sx = fmaf(e, (float)(2 * cc2 + j), sx);
        }
    }
    __syncthreads();
#pragma unroll
    for (int o = 16; o; o >>= 1) {
        se += __shfl_xor_sync(0xffffffffu, se, o);
        sy += __shfl_xor_sync(0xffffffffu, sy, o);
        sx += __shfl_xor_sync(0xffffffffu, sx, o);
    }
    if ((t & 31) == 0) { int w = t >> 5; s_red[w] = se; s_red[8 + w] = sy; s_red[16 + w] = sx; }
    __syncthreads();
    if (t == 0) {
        float Se = 0, Sy = 0, Sx = 0;
        for (int i = 0; i < 8; i++) { Se += s_red[i]; Sy += s_red[8 + i]; Sx += s_red[16 + i]; }
        g_pos[q * 2 + 0] = (Sx / Se) * 8.f;
        g_pos[q * 2 + 1] = (Sy / Se) * 8.f;
    }
    __syncthreads();

    if (t < 16) {
        float a = s_b4[t];
        for (int ic = 0; ic < 32; ic++) a = fmaf(s_o3[ic] * (1.f / 1024.f), s_w4[ic * 16 + t], a);
        s_h4[t] = fmaxf(a, 0.f);
    }
    __syncthreads();
    if (t == 0) {
        float o = s_ob[0], ex2 = s_ob[1];
        for (int k = 0; k < 16; k++) {
            o   = fmaf(s_h4[k], s_ow[k * 2 + 0], o);
            ex2 = fmaf(s_h4[k], s_ow[k * 2 + 1], ex2);
        }
        g_occv[q] = o;
        g_expd[q] = ex2;
    }
}

// ---------------- correlation (fp32 grids, ILP-4, verified) ----------------
__global__ __launch_bounds__(256) void k_corr(const float* __restrict__ hg,
                                              const float* __restrict__ fg) {
    __shared__ float s_q[384];
    __shared__ float s_D[64];
    int q = blockIdx.x, t = threadIdx.x;
    float px = g_pos[q * 2 + 0], py = g_pos[q * 2 + 1];
    for (int i = t; i < 384; i += 256) s_q[i] = g_feats[q * 384 + i];
    __nv_bfloat16* mih = g_mlpinh + q * MI_STRIDE;
    if (t == 0) {
        mih[0] = __float2bfloat16(0.f);
        mih[1] = __float2bfloat16(0.f);
        mih[2] = __float2bfloat16(g_occv[q]);
        mih[3] = __float2bfloat16(g_expd[q]);
    }
    if (t >= 246 && t < 255) mih[535 + (t - 246)] = __float2bfloat16(0.f);
    for (int i = t; i < 384; i += 256) mih[4 + i] = __float2bfloat16(g_feats[q * 384 + i]);
    __syncthreads();

    const float* Gs[3] = { hg, fg, g_fgavg };
    const int Hs[3] = { 128, 64, 32 };
    const int Cs[3] = { 128, 256, 256 };
    const int QO[3] = { 0, 128, 128 };

    int wrp = t >> 5, lane = t & 31;
#pragma unroll
    for (int l = 0; l < 3; l++) {
        const float* G = Gs[l];
        const int H = Hs[l], C = Cs[l], qo = QO[l];
        float sc = (float)H / 512.f;
        float gy = py * sc, gx = px * sc;
        float y0f = floorf(gy), x0f = floorf(gx);
        float wy = gy - y0f, wx = gx - x0f;
        int y0 = (int)y0f, x0 = (int)x0f;
        const float* sq = s_q + qo;

#pragma unroll
        for (int pp = 0; pp < 8; pp++) {
            int p = wrp + pp * 8;
            int ry = min(max(y0 + (p >> 3) - 3, 0), H - 1);
            int rx = min(max(x0 + (p & 7) - 3, 0), H - 1);
            const float* gp = G + (ry * H + rx) * C;
            float s0 = gp[lane] * sq[lane];
            float s1 = gp[lane + 32] * sq[lane + 32];
            float s2 = gp[lane + 64] * sq[lane + 64];
            float s3 = gp[lane + 96] * sq[lane + 96];
            if (C == 256) {
                s0 = fmaf(gp[lane + 128], sq[lane + 128], s0);
                s1 = fmaf(gp[lane + 160], sq[lane + 160], s1);
                s2 = fmaf(gp[lane + 192], sq[lane + 192], s2);
                s3 = fmaf(gp[lane + 224], sq[lane + 224], s3);
            }
            float s = (s0 + s1) + (s2 + s3);
#pragma unroll
            for (int o = 16; o; o >>= 1) s += __shfl_xor_sync(0xffffffffu, s, o);
            if (lane == 0) s_D[p] = s;
        }
        __syncthreads();
        if (t < 49) {
            int r = t / 7, c2 = t - r * 7;
            float d00 = s_D[r * 8 + c2],       d01 = s_D[r * 8 + c2 + 1];
            float d10 = s_D[(r + 1) * 8 + c2], d11 = s_D[(r + 1) * 8 + c2 + 1];
            float corr = (1.f - wy) * (1.f - wx) * d00 + (1.f - wy) * wx * d01
                       + wy * (1.f - wx) * d10 + wy * wx * d11;
            mih[388 + l * 49 + t] = __float2bfloat16(corr);
        }
        __syncthreads();
    }
}

// ---------------- GEMM1: 32M x 64N tiles, 256 CTAs ----------------
#define AS_S 40
__global__ __launch_bounds__(256) void k_gemm1(const float* __restrict__ bias) {
    __shared__ __align__(16) __nv_bfloat16 As[2][32 * AS_S];
    __shared__ __align__(16) __nv_bfloat16 Bs[2][64 * AS_S];
    int n0 = blockIdx.x * 64, m0 = blockIdx.y * 32, t = threadIdx.x;
    int w = t >> 5, lane = t & 31, qd = lane & 3, g = lane >> 2;
    int wm = (w & 1) * 16, wn = (w >> 1) * 16;
    int fmB = t >> 2, fk = (t & 3) * 8;
    int fmA = t >> 2;
    bool afill = (t < 128);
    float acc[2][4];
#pragma unroll
    for (int nt = 0; nt < 2; nt++)
#pragma unroll
        for (int u = 0; u < 4; u++) acc[nt][u] = 0.f;

    const int NS = 17;
    if (afill)
        *(uint4*)&As[0][fmA * AS_S + fk] = *(const uint4*)&g_mlpinh[(m0 + fmA) * MI_STRIDE + fk];
    *(uint4*)&Bs[0][fmB * AS_S + fk] = *(const uint4*)&g_miwh[(n0 + fmB) * 544 + fk];
    __syncthreads();

    for (int st = 0; st < NS; st++) {
        int cur = st & 1;
        if (st + 1 < NS) {
            int nb = (st + 1) & 1, k0 = (st + 1) * 32;
            if (afill)
                *(uint4*)&As[nb][fmA * AS_S + fk] = *(const uint4*)&g_mlpinh[(m0 + fmA) * MI_STRIDE + k0 + fk];
            *(uint4*)&Bs[nb][fmB * AS_S + fk] = *(const uint4*)&g_miwh[(n0 + fmB) * 544 + k0 + fk];
        }
#pragma unroll
        for (int s = 0; s < 2; s++) {
            unsigned a[4], b[2][2];
            int row = wm + g;
            a[0] = *(const unsigned*)&As[cur][row * AS_S + s * 16 + 2 * qd];
            a[1] = *(const unsigned*)&As[cur][(row + 8) * AS_S + s * 16 + 2 * qd];
            a[2] = *(const unsigned*)&As[cur][row * AS_S + s * 16 + 2 * qd + 8];
            a[3] = *(const unsigned*)&As[cur][(row + 8) * AS_S + s * 16 + 2 * qd + 8];
#pragma unroll
            for (int nt = 0; nt < 2; nt++) {
                int bn = wn + nt * 8 + g;
                b[nt][0] = *(const unsigned*)&Bs[cur][bn * AS_S + s * 16 + 2 * qd];
                b[nt][1] = *(const unsigned*)&Bs[cur][bn * AS_S + s * 16 + 2 * qd + 8];
            }
#pragma unroll
            for (int nt = 0; nt < 2; nt++)
                mma_bf16(acc[nt][0], acc[nt][1], acc[nt][2], acc[nt][3],
                         a[0], a[1], a[2], a[3], b[nt][0], b[nt][1]);
        }
        __syncthreads();
    }
#pragma unroll
    for (int nt = 0; nt < 2; nt++) {
        int mg = m0 + wm + g;
        int ng = n0 + wn + nt * 8 + qd * 2;
        float bz0 = bias[ng], bz1 = bias[ng + 1];
        unsigned h0 = packbf(gelu_tanh(acc[nt][0] + bz0), gelu_tanh(acc[nt][1] + bz1));
        unsigned h1 = packbf(gelu_tanh(acc[nt][2] + bz0), gelu_tanh(acc[nt][3] + bz1));
        *(unsigned*)&g_hidh[mg * 512 + ng] = h0;
        *(unsigned*)&g_hidh[(mg + 8) * 512 + ng] = h1;
    }
}

// ---------------- GEMM2: 32M x 64N tiles, 224 CTAs (last=1: emits output) ----------------
__global__ __launch_bounds__(256) void k_gemm2(const float* __restrict__ bias,
                                               float* __restrict__ out, int last) {
    __shared__ __align__(16) __nv_bfloat16 As[2][32 * AS_S];
    __shared__ __align__(16) __nv_bfloat16 Bs[2][64 * AS_S];
    int n0 = blockIdx.x * 64, m0 = blockIdx.y * 32, t = threadIdx.x;
    int w = t >> 5, lane = t & 31, qd = lane & 3, g = lane >> 2;
    int wm = (w & 1) * 16, wn = (w >> 1) * 16;
    int fmB = t >> 2, fk = (t & 3) * 8;
    int fmA = t >> 2;
    bool afill = (t < 128);
    float acc[2][4];
#pragma unroll
    for (int nt = 0; nt < 2; nt++)
#pragma unroll
        for (int u = 0; u < 4; u++) acc[nt][u] = 0.f;

    const int NS = 16;
    if (afill)
        *(uint4*)&As[0][fmA * AS_S + fk] = *(const uint4*)&g_hidh[(m0 + fmA) * 512 + fk];
    *(uint4*)&Bs[0][fmB * AS_S + fk] = *(const uint4*)&g_mowh[(n0 + fmB) * 512 + fk];
    __syncthreads();

    for (int st = 0; st < NS; st++) {
        int cur = st & 1;
        if (st + 1 < NS) {
            int nb = (st + 1) & 1, k0 = (st + 1) * 32;
            if (afill)
                *(uint4*)&As[nb][fmA * AS_S + fk] = *(const uint4*)&g_hidh[(m0 + fmA) * 512 + k0 + fk];
            *(uint4*)&Bs[nb][fmB * AS_S + fk] = *(const uint4*)&g_mowh[(n0 + fmB) * 512 + k0 + fk];
        }
#pragma unroll
        for (int s = 0; s < 2; s++) {
            unsigned a[4], b[2][2];
            int row = wm + g;
            a[0] = *(const unsigned*)&As[cur][row * AS_S + s * 16 + 2 * qd];
            a[1] = *(const unsigned*)&As[cur][(row + 8) * AS_S + s * 16 + 2 * qd];
            a[2] = *(const unsigned*)&As[cur][row * AS_S + s * 16 + 2 * qd + 8];
            a[3] = *(const unsigned*)&As[cur][(row + 8) * AS_S + s * 16 + 2 * qd + 8];
#pragma unroll
            for (int nt = 0; nt < 2; nt++) {
                int bn = wn + nt * 8 + g;
                b[nt][0] = *(const unsigned*)&Bs[cur][bn * AS_S + s * 16 + 2 * qd];
                b[nt][1] = *(const unsigned*)&Bs[cur][bn * AS_S + s * 16 + 2 * qd + 8];
            }
#pragma unroll
            for (int nt = 0; nt < 2; nt++)
                mma_bf16(acc[nt][0], acc[nt][1], acc[nt][2], acc[nt][3],
                         a[0], a[1], a[2], a[3], b[nt][0], b[nt][1]);
        }
        __syncthreads();
    }
#pragma unroll
    for (int nt = 0; nt < 2; nt++) {
#pragma unroll
        for (int rr = 0; rr < 2; rr++) {
            int mg = m0 + wm + g + rr * 8;
#pragma unroll
            for (int jj = 0; jj < 2; jj++) {
                int ng = n0 + wn + nt * 8 + qd * 2 + jj;
                if (ng < 388) {
                    float v = acc[nt][rr * 2 + jj] + bias[ng];
                    if (ng < 2) {
                        float nv = g_pos[mg * 2 + ng] + v;
                        g_pos[mg * 2 + ng] = nv;
                        if (last) out[mg * 4 + ng] = nv;
                    } else if (ng == 2) {
                        float nv = g_occv[mg] + v;
                        g_occv[mg] = nv;
                        if (last) out[mg * 4 + 2] = nv;
                    } else if (ng == 3) {
                        float nv = g_expd[mg] + v;
                        g_expd[mg] = nv;
                        if (last) out[mg * 4 + 3] = nv;
                    } else {
                        g_feats[mg * 384 + ng - 4] += v;
                    }
                }
            }
        }
    }
}

// ---------------- launch ----------------
extern "C" void kernel_launch(void* const* d_in, const int* in_sizes, int n_in,
                              void* d_out, int out_size) {
    const float* fg   = (const float*)d_in[0];
    const float* hg   = (const float*)d_in[1];
    const float* qf   = (const float*)d_in[2];
    const float* hq   = (const float*)d_in[3];
    const float* w1   = (const float*)d_in[4];
    const float* b1   = (const float*)d_in[5];
    const float* w2   = (const float*)d_in[6];
    const float* b2   = (const float*)d_in[7];
    const float* w3   = (const float*)d_in[8];
    const float* b3   = (const float*)d_in[9];
    const float* w4   = (const float*)d_in[10];
    const float* b4   = (const float*)d_in[11];
    const float* occw = (const float*)d_in[12];
    const float* occb = (const float*)d_in[13];
    const float* miw  = (const float*)d_in[14];
    const float* mib  = (const float*)d_in[15];
    const float* mow  = (const float*)d_in[16];
    const float* mob  = (const float*)d_in[17];
    float* out = (float*)d_out;

    const int smem_head = 18754 * 4;
    cudaFuncSetAttribute(k_head, cudaFuncAttributeMaxDynamicSharedMemorySize, smem_head);

    k_cv<<<dim3(64, 16), 256>>>(qf, fg, g_cv);
    k_fgavg<<<1024, 256>>>(fg, g_fgavg);
    k_prep<<<960, 256>>>(miw, mow);
    k_head<<<NQ, 256, smem_head>>>(g_cv, hq, qf, w1, b1, w2, b2, w3, b3, w4, b4, occw, occb);

    for (int it = 0; it < 4; it++) {
        k_corr<<<NQ, 256>>>(hg, fg);
        k_gemm1<<<dim3(8, 32), 256>>>(mib);
        k_gemm2<<<dim3(7, 32), 256>>>(mob, out, it == 3 ? 1 : 0);
    }
}

// round 16
// speedup vs baseline: 1.0454x; 1.0454x over previous
#include <cuda_runtime.h>
#include <cuda_bf16.h>
#include <math.h>

#define NQ 1024
#define MI_STRIDE 544

// ---------------- scratch (device globals; no allocation) ----------------
__device__ float g_cv[NQ * 4096];
__device__ float g_pos[NQ * 2];
__device__ float g_occv[NQ];
__device__ float g_expd[NQ];
__device__ float g_feats[NQ * 384];
__device__ float g_fgavg[32 * 32 * 256];
__device__ __nv_bfloat16 g_mlpinh[NQ * MI_STRIDE];
__device__ __nv_bfloat16 g_hidh[NQ * 512];
__device__ __nv_bfloat16 g_miwh[512 * 544];
__device__ __nv_bfloat16 g_mowh[448 * 512];

__device__ __forceinline__ float gelu_tanh(float x) {
    float x3 = x * x * x;
    return 0.5f * x * (1.f + tanhf(0.7978845608028654f * (x + 0.044715f * x3)));
}

__device__ __forceinline__ float tf32r(float x) {
    unsigned u;
    asm("cvt.rna.tf32.f32 %0, %1;" : "=r"(u) : "f"(x));
    return __uint_as_float(u);
}

__device__ __forceinline__ unsigned packbf(float lo, float hi) {
    __nv_bfloat162 v = __floats2bfloat162_rn(lo, hi);
    return *(unsigned*)&v;
}

__device__ __forceinline__ void mma_tf32(float& d0, float& d1, float& d2, float& d3,
                                         float a0, float a1, float a2, float a3,
                                         float b0, float b1) {
    asm("mma.sync.aligned.m16n8k8.row.col.f32.tf32.tf32.f32 "
        "{%0,%1,%2,%3},{%4,%5,%6,%7},{%8,%9},{%0,%1,%2,%3};"
        : "+f"(d0), "+f"(d1), "+f"(d2), "+f"(d3)
        : "r"(__float_as_uint(a0)), "r"(__float_as_uint(a1)),
          "r"(__float_as_uint(a2)), "r"(__float_as_uint(a3)),
          "r"(__float_as_uint(b0)), "r"(__float_as_uint(b1)));
}

__device__ __forceinline__ void mma_bf16(float& d0, float& d1, float& d2, float& d3,
                                         unsigned a0, unsigned a1, unsigned a2, unsigned a3,
                                         unsigned b0, unsigned b1) {
    asm("mma.sync.aligned.m16n8k16.row.col.f32.bf16.bf16.f32 "
        "{%0,%1,%2,%3},{%4,%5,%6,%7},{%8,%9},{%0,%1,%2,%3};"
        : "+f"(d0), "+f"(d1), "+f"(d2), "+f"(d3)
        : "r"(a0), "r"(a1), "r"(a2), "r"(a3), "r"(b0), "r"(b1));
}

// ---------------- one-time weight convert+transpose ----------------
__global__ void k_prep(const float* __restrict__ miw, const float* __restrict__ mow) {
    int n = blockIdx.x, t = threadIdx.x;
    if (n < 512) {
        for (int k = t; k < 544; k += 256)
            g_miwh[n * 544 + k] = __float2bfloat16(k < 535 ? miw[k * 512 + n] : 0.f);
    } else {
        int nn = n - 512;
        for (int k = t; k < 512; k += 256)
            g_mowh[nn * 512 + k] = __float2bfloat16(nn < 388 ? mow[k * 388 + nn] : 0.f);
    }
}

// ---------------- cv = qf @ fg^T (tf32 mma) ----------------
__global__ __launch_bounds__(256) void k_cv(const float* __restrict__ A,
                                            const float* __restrict__ B,
                                            float* __restrict__ C) {
    __shared__ float As[64 * 17];
    __shared__ float Bs[16 * 73];
    int n0 = blockIdx.x * 64, m0 = blockIdx.y * 64, t = threadIdx.x;
    int w = t >> 5, lane = t & 31, qd = lane & 3, g = lane >> 2;
    int wm = (w >> 2) * 32, wn = (w & 3) * 16;
    int mm = t >> 2, k4 = (t & 3) * 4;
    float acc[2][2][4];
#pragma unroll
    for (int mt = 0; mt < 2; mt++)
#pragma unroll
        for (int nt = 0; nt < 2; nt++)
#pragma unroll
            for (int u = 0; u < 4; u++) acc[mt][nt][u] = 0.f;

    for (int k0 = 0; k0 < 256; k0 += 16) {
        float4 va = *(const float4*)&A[(m0 + mm) * 256 + k0 + k4];
        As[mm * 17 + k4 + 0] = tf32r(va.x);
        As[mm * 17 + k4 + 1] = tf32r(va.y);
        As[mm * 17 + k4 + 2] = tf32r(va.z);
        As[mm * 17 + k4 + 3] = tf32r(va.w);
        float4 vb = *(const float4*)&B[(n0 + mm) * 256 + k0 + k4];
        Bs[(k4 + 0) * 73 + mm] = tf32r(vb.x);
        Bs[(k4 + 1) * 73 + mm] = tf32r(vb.y);
        Bs[(k4 + 2) * 73 + mm] = tf32r(vb.z);
        Bs[(k4 + 3) * 73 + mm] = tf32r(vb.w);
        __syncthreads();
#pragma unroll
        for (int s = 0; s < 2; s++) {
            float a[2][4], b[2][2];
#pragma unroll
            for (int mt = 0; mt < 2; mt++) {
                int row = wm + mt * 16 + g;
                a[mt][0] = As[row * 17 + s * 8 + qd];
                a[mt][1] = As[(row + 8) * 17 + s * 8 + qd];
                a[mt][2] = As[row * 17 + s * 8 + qd + 4];
                a[mt][3] = As[(row + 8) * 17 + s * 8 + qd + 4];
            }
#pragma unroll
            for (int nt = 0; nt < 2; nt++) {
                int bn = wn + nt * 8 + g;
                b[nt][0] = Bs[(s * 8 + qd) * 73 + bn];
                b[nt][1] = Bs[(s * 8 + qd + 4) * 73 + bn];
            }
#pragma unroll
            for (int mt = 0; mt < 2; mt++)
#pragma unroll
                for (int nt = 0; nt < 2; nt++)
                    mma_tf32(acc[mt][nt][0], acc[mt][nt][1], acc[mt][nt][2], acc[mt][nt][3],
                             a[mt][0], a[mt][1], a[mt][2], a[mt][3], b[nt][0], b[nt][1]);
        }
        __syncthreads();
    }
#pragma unroll
    for (int mt = 0; mt < 2; mt++)
#pragma unroll
        for (int nt = 0; nt < 2; nt++) {
            int mg = m0 + wm + mt * 16 + g;
            int ng = n0 + wn + nt * 8 + qd * 2;
            *(float2*)&C[mg * 4096 + ng] = make_float2(acc[mt][nt][0], acc[mt][nt][1]);
            *(float2*)&C[(mg + 8) * 4096 + ng] = make_float2(acc[mt][nt][2], acc[mt][nt][3]);
        }
}

// ---------------- fg_avg (2x2 mean pool) ----------------
__global__ void k_fgavg(const float* __restrict__ fg, float* __restrict__ out) {
    int b = blockIdx.x;
    int y = b >> 5, x = b & 31, t = threadIdx.x;
    const float* p = fg + ((2 * y) * 64 + 2 * x) * 256;
    float v = p[t] + p[256 + t] + p[64 * 256 + t] + p[64 * 256 + 256 + t];
    out[(y * 32 + x) * 256 + t] = 0.25f * v;
}

// ---------------- per-query head (CV_S 68, OC_S 68, data col offset 1) ----------------
#define CV_S 68
#define OC_S 68
__global__ __launch_bounds__(256, 3) void k_head(
    const float* __restrict__ cv_g, const float* __restrict__ hq, const float* __restrict__ qf,
    const float* __restrict__ w1, const float* __restrict__ b1,
    const float* __restrict__ w2, const float* __restrict__ b2,
    const float* __restrict__ w3, const float* __restrict__ b3,
    const float* __restrict__ w4, const float* __restrict__ b4,
    const float* __restrict__ occw, const float* __restrict__ occb) {
    extern __shared__ float sm[];
    float* s_cv   = sm;                       // 66*68 = 4488
    float* s_occ  = s_cv + 4488;              // 160*68 = 10880
    unsigned* s_w3b = (unsigned*)(s_occ + 10880); // 72*36 = 2592, [kr][g*4+nt]
    float* s_ko   = (float*)(s_w3b + 2592);   // 144
    float* s_w2   = s_ko + 144;               // 192
    float* s_w4   = s_w2 + 192;               // 512
    float* s_b3   = s_w4 + 512;               // 32
    float* s_b4   = s_b3 + 32;                // 16
    float* s_ow   = s_b4 + 16;                // 32
    float* s_ob   = s_ow + 32;                // 2
    float* s_red  = s_ob + 2;                 // 32
    float* s_o3   = s_red + 32;               // 32
    float* s_h4   = s_o3 + 32;                // 16
    int* s_koi = (int*)s_ko;

    int q = blockIdx.x, t = threadIdx.x;
    const float* cvq = cv_g + q * 4096;
    for (int i = t; i < 4096; i += 256) s_cv[(1 + (i >> 6)) * CV_S + 1 + (i & 63)] = cvq[i];
    if (t < 68) { s_cv[t] = 0.f; s_cv[65 * CV_S + t] = 0.f; }
    if (t < 64) {
        s_cv[(t + 1) * CV_S] = 0.f;
        s_cv[(t + 1) * CV_S + 65] = 0.f;
        s_cv[(t + 1) * CV_S + 66] = 0.f;
    }
    for (int i = t; i < 160; i += 256) {
        float* rb = &s_occ[i * OC_S];
        rb[0] = 0.f; rb[65] = 0.f; rb[66] = 0.f; rb[67] = 0.f;
    }
    for (int i = t; i < 144; i += 256) { int c = i / 9, k = i - c * 9; s_w2[c * 12 + k] = w2[i]; }
    // w3 repack: [kr][ (oc&7)*4 + (oc>>3) ], so per (kr,g) the 4 nt values are one uint4
    for (int i = t; i < 72 * 32; i += 256) {
        int krow = i >> 5, oc = i & 31;
        int k = krow * 2;
        s_w3b[krow * 36 + (oc & 7) * 4 + (oc >> 3)] = packbf(w3[oc * 144 + k], w3[oc * 144 + k + 1]);
    }
    for (int i = t; i < 144; i += 256) {
        int ic = i / 9, rk = i - ic * 9;
        int dy = rk / 3, dx = rk - dy * 3;
        s_koi[i] = (dy * 16 + ic) * OC_S + dx;
    }
    for (int i = t; i < 512; i += 256) s_w4[i] = w4[i];
    if (t < 32) s_b3[t] = b3[t];
    if (t < 16) s_b4[t] = b4[t];
    if (t < 32) s_ow[t] = occw[t];
    if (t < 2)  s_ob[t] = occb[t];
    if (t < 32) s_o3[t] = 0.f;
    for (int i = t; i < 128; i += 256) g_feats[q * 384 + i] = hq[q * 128 + i];
    for (int i = t; i < 256; i += 256) g_feats[q * 384 + 128 + i] = qf[q * 256 + i];
    float b2v = b2[0];

    int c1 = t & 15, xg = (t >> 4) & 7, sl2 = t >> 7;
    int x0 = xg * 8;
    float w1r[9], b1r = b1[c1];
#pragma unroll
    for (int k = 0; k < 9; k++) w1r[k] = w1[c1 * 9 + k];

    // conv2 mapping (R14): t<128 active, rr2 = (t>>4)&7, cg2 = t&15, 4 cols
    int rr2 = (t >> 4) & 7, cg2 = t & 15;
    bool c2act = (t < 128);
    float pm[32];

    int wrp = t >> 5, lane = t & 31, qd = lane & 3, g = lane >> 2;
    int jrow3 = wrp >> 1;
    int col0 = (wrp & 1) * 16 + g;
    int base0 = (2 * jrow3 + 1) * (16 * OC_S) + 2 * col0 + 1;
    float macc[4][2];
#pragma unroll
    for (int nt = 0; nt < 4; nt++) { macc[nt][0] = 0.f; macc[nt][1] = 0.f; }

    __syncthreads();

    float b3n[4][2];
#pragma unroll
    for (int nt = 0; nt < 4; nt++) {
        b3n[nt][0] = s_b3[nt * 8 + qd * 2 + 0];
        b3n[nt][1] = s_b3[nt * 8 + qd * 2 + 1];
    }

    for (int r0 = 0; r0 < 64; r0 += 8) {
        int band = r0 >> 3;
#pragma unroll
        for (int s = 0; s < 5; s++) {
            int slot = sl2 + 2 * s;
            int row = r0 - 1 + slot;
            float* dst = &s_occ[(slot * 16 + c1) * OC_S + 1 + x0];
            if (row < 0 || row > 63) {
#pragma unroll
                for (int j = 0; j < 8; j++) dst[j] = 0.f;
                continue;
            }
            float xv[3][10];
#pragma unroll
            for (int dy = 0; dy < 3; dy++) {
                const float* rp = &s_cv[(row + dy) * CV_S + x0];
                float4 vA = *(const float4*)rp;
                float4 vB = *(const float4*)(rp + 4);
                float2 vC = *(const float2*)(rp + 8);
                xv[dy][0] = vA.x; xv[dy][1] = vA.y; xv[dy][2] = vA.z; xv[dy][3] = vA.w;
                xv[dy][4] = vB.x; xv[dy][5] = vB.y; xv[dy][6] = vB.z; xv[dy][7] = vB.w;
                xv[dy][8] = vC.x; xv[dy][9] = vC.y;
            }
#pragma unroll
            for (int j = 0; j < 8; j++) {
                float a = b1r;
#pragma unroll
                for (int dy = 0; dy < 3; dy++)
#pragma unroll
                    for (int dx = 0; dx < 3; dx++)
                        a = fmaf(w1r[dy * 3 + dx], xv[dy][j + dx], a);
                dst[j] = fmaxf(a, 0.f);
            }
        }
        __syncthreads();

        // ---- conv2 (R14 mapping): t<128, rows r0+rr2, cols 4cg2..4cg2+3 ----
        if (c2act) {
            float a[4] = {b2v, b2v, b2v, b2v};
#pragma unroll
            for (int c = 0; c < 16; c++) {
                float4 wA = *(const float4*)&s_w2[c * 12];
                float4 wB = *(const float4*)&s_w2[c * 12 + 4];
                float w8 = s_w2[c * 12 + 8];
                float wv[9] = {wA.x, wA.y, wA.z, wA.w, wB.x, wB.y, wB.z, wB.w, w8};
#pragma unroll
                for (int dy = 0; dy < 3; dy++) {
                    const float* rp = &s_occ[((rr2 + dy) * 16 + c) * OC_S + 4 * cg2];
                    float4 vA = *(const float4*)rp;
                    float2 vB = *(const float2*)(rp + 4);
                    float v[6] = {vA.x, vA.y, vA.z, vA.w, vB.x, vB.y};
#pragma unroll
                    for (int j = 0; j < 4; j++)
                        a[j] = fmaf(wv[dy * 3 + 0], v[j],
                               fmaf(wv[dy * 3 + 1], v[j + 1],
                               fmaf(wv[dy * 3 + 2], v[j + 2], a[j])));
                }
            }
#pragma unroll
            for (int j = 0; j < 4; j++) pm[band * 4 + j] = a[j];
        }

        // ---- conv3 via bf16 mma (k16): 9 steps, uint4 weight loads ----
        {
            float d[4][4];
#pragma unroll
            for (int nt = 0; nt < 4; nt++)
#pragma unroll
                for (int u = 0; u < 4; u++) d[nt][u] = 0.f;

#pragma unroll
            for (int st = 0; st < 9; st++) {
                int kE = st * 16 + 2 * qd;
                int kO = kE + 8;
                int e0 = s_koi[kE], e1 = s_koi[kE + 1];
                int o0 = s_koi[kO], o1 = s_koi[kO + 1];
                unsigned a0 = packbf(s_occ[base0 + e0],      s_occ[base0 + e1]);
                unsigned a1 = packbf(s_occ[base0 + 16 + e0], s_occ[base0 + 16 + e1]);
                unsigned a2 = packbf(s_occ[base0 + o0],      s_occ[base0 + o1]);
                unsigned a3 = packbf(s_occ[base0 + 16 + o0], s_occ[base0 + 16 + o1]);
                int kr = st * 8 + qd;
                uint4 bw0 = *(const uint4*)&s_w3b[kr * 36 + g * 4];
                uint4 bw1 = *(const uint4*)&s_w3b[(kr + 4) * 36 + g * 4];
                mma_bf16(d[0][0], d[0][1], d[0][2], d[0][3], a0, a1, a2, a3, bw0.x, bw1.x);
                mma_bf16(d[1][0], d[1][1], d[1][2], d[1][3], a0, a1, a2, a3, bw0.y, bw1.y);
                mma_bf16(d[2][0], d[2][1], d[2][2], d[2][3], a0, a1, a2, a3, bw0.z, bw1.z);
                mma_bf16(d[3][0], d[3][1], d[3][2], d[3][3], a0, a1, a2, a3, bw0.w, bw1.w);
            }
#pragma unroll
            for (int nt = 0; nt < 4; nt++) {
                macc[nt][0] += fmaxf(d[nt][0] + b3n[nt][0], 0.f) + fmaxf(d[nt][2] + b3n[nt][0], 0.f);
                macc[nt][1] += fmaxf(d[nt][1] + b3n[nt][1], 0.f) + fmaxf(d[nt][3] + b3n[nt][1], 0.f);
            }
        }
        __syncthreads();
    }

#pragma unroll
    for (int nt = 0; nt < 4; nt++) {
#pragma unroll
        for (int j = 0; j < 2; j++) {
            float v = macc[nt][j];
#pragma unroll
            for (int o = 4; o <= 16; o <<= 1) v += __shfl_xor_sync(0xffffffffu, v, o);
            if (g == 0) atomicAdd(&s_o3[nt * 8 + qd * 2 + j], v);
        }
    }

    float lmax = -1e30f;
    if (c2act) {
#pragma unroll
        for (int u = 0; u < 32; u++) lmax = fmaxf(lmax, pm[u]);
    }
#pragma unroll
    for (int o = 16; o; o >>= 1) lmax = fmaxf(lmax, __shfl_xor_sync(0xffffffffu, lmax, o));
    if ((t & 31) == 0) s_red[t >> 5] = lmax;
    __syncthreads();
    if (t == 0) {
        float m = s_red[0];
        for (int i = 1; i < 8; i++) m = fmaxf(m, s_red[i]);
        s_red[31] = m;
    }
    __syncthreads();
    float m = s_red[31];
    float se = 0.f, sy = 0.f, sx = 0.f;
    if (c2act) {
#pragma unroll
        for (int b = 0; b < 8; b++) {
            float rowf = (float)(8 * b + rr2);
#pragma unroll
            for (int j = 0; j < 4; j++) {
                float e = __expf((pm[b * 4 + j] - m) * 20.f);
                se += e;
                sy = fmaf(e, rowf, sy);
                sx = fmaf(e, (float)(4 * cg2 + j), sx);
            }
        }
    }
    __syncthreads();
#pragma unroll
    for (int o = 16; o; o >>= 1) {
        se += __shfl_xor_sync(0xffffffffu, se, o);
        sy += __shfl_xor_sync(0xffffffffu, sy, o);
        sx += __shfl_xor_sync(0xffffffffu, sx, o);
    }
    if ((t & 31) == 0) { int w = t >> 5; s_red[w] = se; s_red[8 + w] = sy; s_red[16 + w] = sx; }
    __syncthreads();
    if (t == 0) {
        float Se = 0, Sy = 0, Sx = 0;
        for (int i = 0; i < 8; i++) { Se += s_red[i]; Sy += s_red[8 + i]; Sx += s_red[16 + i]; }
        g_pos[q * 2 + 0] = (Sx / Se) * 8.f;
        g_pos[q * 2 + 1] = (Sy / Se) * 8.f;
    }
    __syncthreads();

    if (t < 16) {
        float a = s_b4[t];
        for (int ic = 0; ic < 32; ic++) a = fmaf(s_o3[ic] * (1.f / 1024.f), s_w4[ic * 16 + t], a);
        s_h4[t] = fmaxf(a, 0.f);
    }
    __syncthreads();
    if (t == 0) {
        float o = s_ob[0], ex2 = s_ob[1];
        for (int k = 0; k < 16; k++) {
            o   = fmaf(s_h4[k], s_ow[k * 2 + 0], o);
            ex2 = fmaf(s_h4[k], s_ow[k * 2 + 1], ex2);
        }
        g_occv[q] = o;
        g_expd[q] = ex2;
    }
}

// ---------------- correlation (fp32 grids, ILP-4, verified) ----------------
__global__ __launch_bounds__(256) void k_corr(const float* __restrict__ hg,
                                              const float* __restrict__ fg) {
    __shared__ float s_q[384];
    __shared__ float s_D[64];
    int q = blockIdx.x, t = threadIdx.x;
    float px = g_pos[q * 2 + 0], py = g_pos[q * 2 + 1];
    for (int i = t; i < 384; i += 256) s_q[i] = g_feats[q * 384 + i];
    __nv_bfloat16* mih = g_mlpinh + q * MI_STRIDE;
    if (t == 0) {
        mih[0] = __float2bfloat16(0.f);
        mih[1] = __float2bfloat16(0.f);
        mih[2] = __float2bfloat16(g_occv[q]);
        mih[3] = __float2bfloat16(g_expd[q]);
    }
    if (t >= 246 && t < 255) mih[535 + (t - 246)] = __float2bfloat16(0.f);
    for (int i = t; i < 384; i += 256) mih[4 + i] = __float2bfloat16(g_feats[q * 384 + i]);
    __syncthreads();

    const float* Gs[3] = { hg, fg, g_fgavg };
    const int Hs[3] = { 128, 64, 32 };
    const int Cs[3] = { 128, 256, 256 };
    const int QO[3] = { 0, 128, 128 };

    int wrp = t >> 5, lane = t & 31;
#pragma unroll
    for (int l = 0; l < 3; l++) {
        const float* G = Gs[l];
        const int H = Hs[l], C = Cs[l], qo = QO[l];
        float sc = (float)H / 512.f;
        float gy = py * sc, gx = px * sc;
        float y0f = floorf(gy), x0f = floorf(gx);
        float wy = gy - y0f, wx = gx - x0f;
        int y0 = (int)y0f, x0 = (int)x0f;
        const float* sq = s_q + qo;

#pragma unroll
        for (int pp = 0; pp < 8; pp++) {
            int p = wrp + pp * 8;
            int ry = min(max(y0 + (p >> 3) - 3, 0), H - 1);
            int rx = min(max(x0 + (p & 7) - 3, 0), H - 1);
            const float* gp = G + (ry * H + rx) * C;
            float s0 = gp[lane] * sq[lane];
            float s1 = gp[lane + 32] * sq[lane + 32];
            float s2 = gp[lane + 64] * sq[lane + 64];
            float s3 = gp[lane + 96] * sq[lane + 96];
            if (C == 256) {
                s0 = fmaf(gp[lane + 128], sq[lane + 128], s0);
                s1 = fmaf(gp[lane + 160], sq[lane + 160], s1);
                s2 = fmaf(gp[lane + 192], sq[lane + 192], s2);
                s3 = fmaf(gp[lane + 224], sq[lane + 224], s3);
            }
            float s = (s0 + s1) + (s2 + s3);
#pragma unroll
            for (int o = 16; o; o >>= 1) s += __shfl_xor_sync(0xffffffffu, s, o);
            if (lane == 0) s_D[p] = s;
        }
        __syncthreads();
        if (t < 49) {
            int r = t / 7, c2 = t - r * 7;
            float d00 = s_D[r * 8 + c2],       d01 = s_D[r * 8 + c2 + 1];
            float d10 = s_D[(r + 1) * 8 + c2], d11 = s_D[(r + 1) * 8 + c2 + 1];
            float corr = (1.f - wy) * (1.f - wx) * d00 + (1.f - wy) * wx * d01
                       + wy * (1.f - wx) * d10 + wy * wx * d11;
            mih[388 + l * 49 + t] = __float2bfloat16(corr);
        }
        __syncthreads();
    }
}

// ---------------- GEMM1: 32M x 64N tiles, 256 CTAs ----------------
#define AS_S 40
__global__ __launch_bounds__(256) void k_gemm1(const float* __restrict__ bias) {
    __shared__ __align__(16) __nv_bfloat16 As[2][32 * AS_S];
    __shared__ __align__(16) __nv_bfloat16 Bs[2][64 * AS_S];
    int n0 = blockIdx.x * 64, m0 = blockIdx.y * 32, t = threadIdx.x;
    int w = t >> 5, lane = t & 31, qd = lane & 3, g = lane >> 2;
    int wm = (w & 1) * 16, wn = (w >> 1) * 16;
    int fmB = t >> 2, fk = (t & 3) * 8;
    int fmA = t >> 2;
    bool afill = (t < 128);
    float acc[2][4];
#pragma unroll
    for (int nt = 0; nt < 2; nt++)
#pragma unroll
        for (int u = 0; u < 4; u++) acc[nt][u] = 0.f;

    const int NS = 17;
    if (afill)
        *(uint4*)&As[0][fmA * AS_S + fk] = *(const uint4*)&g_mlpinh[(m0 + fmA) * MI_STRIDE + fk];
    *(uint4*)&Bs[0][fmB * AS_S + fk] = *(const uint4*)&g_miwh[(n0 + fmB) * 544 + fk];
    __syncthreads();

    for (int st = 0; st < NS; st++) {
        int cur = st & 1;
        if (st + 1 < NS) {
            int nb = (st + 1) & 1, k0 = (st + 1) * 32;
            if (afill)
                *(uint4*)&As[nb][fmA * AS_S + fk] = *(const uint4*)&g_mlpinh[(m0 + fmA) * MI_STRIDE + k0 + fk];
            *(uint4*)&Bs[nb][fmB * AS_S + fk] = *(const uint4*)&g_miwh[(n0 + fmB) * 544 + k0 + fk];
        }
#pragma unroll
        for (int s = 0; s < 2; s++) {
            unsigned a[4], b[2][2];
            int row = wm + g;
            a[0] = *(const unsigned*)&As[cur][row * AS_S + s * 16 + 2 * qd];
            a[1] = *(const unsigned*)&As[cur][(row + 8) * AS_S + s * 16 + 2 * qd];
            a[2] = *(const unsigned*)&As[cur][row * AS_S + s * 16 + 2 * qd + 8];
            a[3] = *(const unsigned*)&As[cur][(row + 8) * AS_S + s * 16 + 2 * qd + 8];
#pragma unroll
            for (int nt = 0; nt < 2; nt++) {
                int bn = wn + nt * 8 + g;
                b[nt][0] = *(const unsigned*)&Bs[cur][bn * AS_S + s * 16 + 2 * qd];
                b[nt][1] = *(const unsigned*)&Bs[cur][bn * AS_S + s * 16 + 2 * qd + 8];
            }
#pragma unroll
            for (int nt = 0; nt < 2; nt++)
                mma_bf16(acc[nt][0], acc[nt][1], acc[nt][2], acc[nt][3],
                         a[0], a[1], a[2], a[3], b[nt][0], b[nt][1]);
        }
        __syncthreads();
    }
#pragma unroll
    for (int nt = 0; nt < 2; nt++) {
        int mg = m0 + wm + g;
        int ng = n0 + wn + nt * 8 + qd * 2;
        float bz0 = bias[ng], bz1 = bias[ng + 1];
        unsigned h0 = packbf(gelu_tanh(acc[nt][0] + bz0), gelu_tanh(acc[nt][1] + bz1));
        unsigned h1 = packbf(gelu_tanh(acc[nt][2] + bz0), gelu_tanh(acc[nt][3] + bz1));
        *(unsigned*)&g_hidh[mg * 512 + ng] = h0;
        *(unsigned*)&g_hidh[(mg + 8) * 512 + ng] = h1;
    }
}

// ---------------- GEMM2: 32M x 64N tiles, 224 CTAs (last=1: emits output) ----------------
__global__ __launch_bounds__(256) void k_gemm2(const float* __restrict__ bias,
                                               float* __restrict__ out, int last) {
    __shared__ __align__(16) __nv_bfloat16 As[2][32 * AS_S];
    __shared__ __align__(16) __nv_bfloat16 Bs[2][64 * AS_S];
    int n0 = blockIdx.x * 64, m0 = blockIdx.y * 32, t = threadIdx.x;
    int w = t >> 5, lane = t & 31, qd = lane & 3, g = lane >> 2;
    int wm = (w & 1) * 16, wn = (w >> 1) * 16;
    int fmB = t >> 2, fk = (t & 3) * 8;
    int fmA = t >> 2;
    bool afill = (t < 128);
    float acc[2][4];
#pragma unroll
    for (int nt = 0; nt < 2; nt++)
#pragma unroll
        for (int u = 0; u < 4; u++) acc[nt][u] = 0.f;

    const int NS = 16;
    if (afill)
        *(uint4*)&As[0][fmA * AS_S + fk] = *(const uint4*)&g_hidh[(m0 + fmA) * 512 + fk];
    *(uint4*)&Bs[0][fmB * AS_S + fk] = *(const uint4*)&g_mowh[(n0 + fmB) * 512 + fk];
    __syncthreads();

    for (int st = 0; st < NS; st++) {
        int cur = st & 1;
        if (st + 1 < NS) {
            int nb = (st + 1) & 1, k0 = (st + 1) * 32;
            if (afill)
                *(uint4*)&As[nb][fmA * AS_S + fk] = *(const uint4*)&g_hidh[(m0 + fmA) * 512 + k0 + fk];
            *(uint4*)&Bs[nb][fmB * AS_S + fk] = *(const uint4*)&g_mowh[(n0 + fmB) * 512 + k0 + fk];
        }
#pragma unroll
        for (int s = 0; s < 2; s++) {
            unsigned a[4], b[2][2];
            int row = wm + g;
            a[0] = *(const unsigned*)&As[cur][row * AS_S + s * 16 + 2 * qd];
            a[1] = *(const unsigned*)&As[cur][(row + 8) * AS_S + s * 16 + 2 * qd];
            a[2] = *(const unsigned*)&As[cur][row * AS_S + s * 16 + 2 * qd + 8];
            a[3] = *(const unsigned*)&As[cur][(row + 8) * AS_S + s * 16 + 2 * qd + 8];
#pragma unroll
            for (int nt = 0; nt < 2; nt++) {
                int bn = wn + nt * 8 + g;
                b[nt][0] = *(const unsigned*)&Bs[cur][bn * AS_S + s * 16 + 2 * qd];
                b[nt][1] = *(const unsigned*)&Bs[cur][bn * AS_S + s * 16 + 2 * qd + 8];
            }
#pragma unroll
            for (int nt = 0; nt < 2; nt++)
                mma_bf16(acc[nt][0], acc[nt][1], acc[nt][2], acc[nt][3],
                         a[0], a[1], a[2], a[3], b[nt][0], b[nt][1]);
        }
        __syncthreads();
    }
#pragma unroll
    for (int nt = 0; nt < 2; nt++) {
#pragma unroll
        for (int rr = 0; rr < 2; rr++) {
            int mg = m0 + wm + g + rr * 8;
#pragma unroll
            for (int jj = 0; jj < 2; jj++) {
                int ng = n0 + wn + nt * 8 + qd * 2 + jj;
                if (ng < 388) {
                    float v = acc[nt][rr * 2 + jj] + bias[ng];
                    if (ng < 2) {
                        float nv = g_pos[mg * 2 + ng] + v;
                        g_pos[mg * 2 + ng] = nv;
                        if (last) out[mg * 4 + ng] = nv;
                    } else if (ng == 2) {
                        float nv = g_occv[mg] + v;
                        g_occv[mg] = nv;
                        if (last) out[mg * 4 + 2] = nv;
                    } else if (ng == 3) {
                        float nv = g_expd[mg] + v;
                        g_expd[mg] = nv;
                        if (last) out[mg * 4 + 3] = nv;
                    } else {
                        g_feats[mg * 384 + ng - 4] += v;
                    }
                }
            }
        }
    }
}

// ---------------- launch ----------------
extern "C" void kernel_launch(void* const* d_in, const int* in_sizes, int n_in,
                              void* d_out, int out_size) {
    const float* fg   = (const float*)d_in[0];
    const float* hg   = (const float*)d_in[1];
    const float* qf   = (const float*)d_in[2];
    const float* hq   = (const float*)d_in[3];
    const float* w1   = (const float*)d_in[4];
    const float* b1   = (const float*)d_in[5];
    const float* w2   = (const float*)d_in[6];
    const float* b2   = (const float*)d_in[7];
    const float* w3   = (const float*)d_in[8];
    const float* b3   = (const float*)d_in[9];
    const float* w4   = (const float*)d_in[10];
    const float* b4   = (const float*)d_in[11];
    const float* occw = (const float*)d_in[12];
    const float* occb = (const float*)d_in[13];
    const float* miw  = (const float*)d_in[14];
    const float* mib  = (const float*)d_in[15];
    const float* mow  = (const float*)d_in[16];
    const float* mob  = (const float*)d_in[17];
    float* out = (float*)d_out;

    // 4488 + 10880 + 2592 + 144 + 192 + 512 + 162 = 18970 floats = 75880 B
    const int smem_head = 18970 * 4;
    cudaFuncSetAttribute(k_head, cudaFuncAttributeMaxDynamicSharedMemorySize, smem_head);

    k_cv<<<dim3(64, 16), 256>>>(qf, fg, g_cv);
    k_fgavg<<<1024, 256>>>(fg, g_fgavg);
    k_prep<<<960, 256>>>(miw, mow);
    k_head<<<NQ, 256, smem_head>>>(g_cv, hq, qf, w1, b1, w2, b2, w3, b3, w4, b4, occw, occb);

    for (int it = 0; it < 4; it++) {
        k_corr<<<NQ, 256>>>(hg, fg);
        k_gemm1<<<dim3(8, 32), 256>>>(mib);
        k_gemm2<<<dim3(7, 32), 256>>>(mob, out, it == 3 ? 1 : 0);
    }
}

// round 17
// speedup vs baseline: 1.0663x; 1.0199x over previous
#include <cuda_runtime.h>
#include <cuda_bf16.h>
#include <math.h>

#define NQ 1024
#define MI_STRIDE 576

// ---------------- scratch (device globals; no allocation) ----------------
__device__ float g_cv[NQ * 4096];
__device__ float g_pos[NQ * 2];
__device__ float g_occv[NQ];
__device__ float g_expd[NQ];
__device__ float g_feats[NQ * 384];
__device__ float g_fgavg[32 * 32 * 256];
__device__ __nv_bfloat16 g_mlpinh[NQ * MI_STRIDE];
__device__ __nv_bfloat16 g_hidh[NQ * 512];
__device__ __nv_bfloat16 g_miwh[512 * 576];
__device__ __nv_bfloat16 g_mowh[448 * 512];

__device__ __forceinline__ float gelu_tanh(float x) {
    float x3 = x * x * x;
    return 0.5f * x * (1.f + tanhf(0.7978845608028654f * (x + 0.044715f * x3)));
}

__device__ __forceinline__ float tf32r(float x) {
    unsigned u;
    asm("cvt.rna.tf32.f32 %0, %1;" : "=r"(u) : "f"(x));
    return __uint_as_float(u);
}

__device__ __forceinline__ unsigned packbf(float lo, float hi) {
    __nv_bfloat162 v = __floats2bfloat162_rn(lo, hi);
    return *(unsigned*)&v;
}

__device__ __forceinline__ void mma_tf32(float& d0, float& d1, float& d2, float& d3,
                                         float a0, float a1, float a2, float a3,
                                         float b0, float b1) {
    asm("mma.sync.aligned.m16n8k8.row.col.f32.tf32.tf32.f32 "
        "{%0,%1,%2,%3},{%4,%5,%6,%7},{%8,%9},{%0,%1,%2,%3};"
        : "+f"(d0), "+f"(d1), "+f"(d2), "+f"(d3)
        : "r"(__float_as_uint(a0)), "r"(__float_as_uint(a1)),
          "r"(__float_as_uint(a2)), "r"(__float_as_uint(a3)),
          "r"(__float_as_uint(b0)), "r"(__float_as_uint(b1)));
}

__device__ __forceinline__ void mma_bf16(float& d0, float& d1, float& d2, float& d3,
                                         unsigned a0, unsigned a1, unsigned a2, unsigned a3,
                                         unsigned b0, unsigned b1) {
    asm("mma.sync.aligned.m16n8k16.row.col.f32.bf16.bf16.f32 "
        "{%0,%1,%2,%3},{%4,%5,%6,%7},{%8,%9},{%0,%1,%2,%3};"
        : "+f"(d0), "+f"(d1), "+f"(d2), "+f"(d3)
        : "r"(a0), "r"(a1), "r"(a2), "r"(a3), "r"(b0), "r"(b1));
}

// ---------------- one-time weight convert+transpose ----------------
__global__ void k_prep(const float* __restrict__ miw, const float* __restrict__ mow) {
    int n = blockIdx.x, t = threadIdx.x;
    if (n < 512) {
        for (int k = t; k < 576; k += 256)
            g_miwh[n * 576 + k] = __float2bfloat16(k < 535 ? miw[k * 512 + n] : 0.f);
    } else {
        int nn = n - 512;
        for (int k = t; k < 512; k += 256)
            g_mowh[nn * 512 + k] = __float2bfloat16(nn < 388 ? mow[k * 388 + nn] : 0.f);
    }
}

// ---------------- cv = qf @ fg^T (tf32 mma) ----------------
__global__ __launch_bounds__(256) void k_cv(const float* __restrict__ A,
                                            const float* __restrict__ B,
                                            float* __restrict__ C) {
    __shared__ float As[64 * 17];
    __shared__ float Bs[16 * 73];
    int n0 = blockIdx.x * 64, m0 = blockIdx.y * 64, t = threadIdx.x;
    int w = t >> 5, lane = t & 31, qd = lane & 3, g = lane >> 2;
    int wm = (w >> 2) * 32, wn = (w & 3) * 16;
    int mm = t >> 2, k4 = (t & 3) * 4;
    float acc[2][2][4];
#pragma unroll
    for (int mt = 0; mt < 2; mt++)
#pragma unroll
        for (int nt = 0; nt < 2; nt++)
#pragma unroll
            for (int u = 0; u < 4; u++) acc[mt][nt][u] = 0.f;

    for (int k0 = 0; k0 < 256; k0 += 16) {
        float4 va = *(const float4*)&A[(m0 + mm) * 256 + k0 + k4];
        As[mm * 17 + k4 + 0] = tf32r(va.x);
        As[mm * 17 + k4 + 1] = tf32r(va.y);
        As[mm * 17 + k4 + 2] = tf32r(va.z);
        As[mm * 17 + k4 + 3] = tf32r(va.w);
        float4 vb = *(const float4*)&B[(n0 + mm) * 256 + k0 + k4];
        Bs[(k4 + 0) * 73 + mm] = tf32r(vb.x);
        Bs[(k4 + 1) * 73 + mm] = tf32r(vb.y);
        Bs[(k4 + 2) * 73 + mm] = tf32r(vb.z);
        Bs[(k4 + 3) * 73 + mm] = tf32r(vb.w);
        __syncthreads();
#pragma unroll
        for (int s = 0; s < 2; s++) {
            float a[2][4], b[2][2];
#pragma unroll
            for (int mt = 0; mt < 2; mt++) {
                int row = wm + mt * 16 + g;
                a[mt][0] = As[row * 17 + s * 8 + qd];
                a[mt][1] = As[(row + 8) * 17 + s * 8 + qd];
                a[mt][2] = As[row * 17 + s * 8 + qd + 4];
                a[mt][3] = As[(row + 8) * 17 + s * 8 + qd + 4];
            }
#pragma unroll
            for (int nt = 0; nt < 2; nt++) {
                int bn = wn + nt * 8 + g;
                b[nt][0] = Bs[(s * 8 + qd) * 73 + bn];
                b[nt][1] = Bs[(s * 8 + qd + 4) * 73 + bn];
            }
#pragma unroll
            for (int mt = 0; mt < 2; mt++)
#pragma unroll
                for (int nt = 0; nt < 2; nt++)
                    mma_tf32(acc[mt][nt][0], acc[mt][nt][1], acc[mt][nt][2], acc[mt][nt][3],
                             a[mt][0], a[mt][1], a[mt][2], a[mt][3], b[nt][0], b[nt][1]);
        }
        __syncthreads();
    }
#pragma unroll
    for (int mt = 0; mt < 2; mt++)
#pragma unroll
        for (int nt = 0; nt < 2; nt++) {
            int mg = m0 + wm + mt * 16 + g;
            int ng = n0 + wn + nt * 8 + qd * 2;
            *(float2*)&C[mg * 4096 + ng] = make_float2(acc[mt][nt][0], acc[mt][nt][1]);
            *(float2*)&C[(mg + 8) * 4096 + ng] = make_float2(acc[mt][nt][2], acc[mt][nt][3]);
        }
}

// ---------------- fg_avg (2x2 mean pool) ----------------
__global__ void k_fgavg(const float* __restrict__ fg, float* __restrict__ out) {
    int b = blockIdx.x;
    int y = b >> 5, x = b & 31, t = threadIdx.x;
    const float* p = fg + ((2 * y) * 64 + 2 * x) * 256;
    float v = p[t] + p[256 + t] + p[64 * 256 + t] + p[64 * 256 + 256 + t];
    out[(y * 32 + x) * 256 + t] = 0.25f * v;
}

// ---------------- per-query head (R16 verified) ----------------
#define CV_S 68
#define OC_S 68
__global__ __launch_bounds__(256, 3) void k_head(
    const float* __restrict__ cv_g, const float* __restrict__ hq, const float* __restrict__ qf,
    const float* __restrict__ w1, const float* __restrict__ b1,
    const float* __restrict__ w2, const float* __restrict__ b2,
    const float* __restrict__ w3, const float* __restrict__ b3,
    const float* __restrict__ w4, const float* __restrict__ b4,
    const float* __restrict__ occw, const float* __restrict__ occb) {
    extern __shared__ float sm[];
    float* s_cv   = sm;                       // 66*68 = 4488
    float* s_occ  = s_cv + 4488;              // 160*68 = 10880
    unsigned* s_w3b = (unsigned*)(s_occ + 10880); // 72*36 = 2592, [kr][g*4+nt]
    float* s_ko   = (float*)(s_w3b + 2592);   // 144
    float* s_w2   = s_ko + 144;               // 192
    float* s_w4   = s_w2 + 192;               // 512
    float* s_b3   = s_w4 + 512;               // 32
    float* s_b4   = s_b3 + 32;                // 16
    float* s_ow   = s_b4 + 16;                // 32
    float* s_ob   = s_ow + 32;                // 2
    float* s_red  = s_ob + 2;                 // 32
    float* s_o3   = s_red + 32;               // 32
    float* s_h4   = s_o3 + 32;                // 16
    int* s_koi = (int*)s_ko;

    int q = blockIdx.x, t = threadIdx.x;
    const float* cvq = cv_g + q * 4096;
    for (int i = t; i < 4096; i += 256) s_cv[(1 + (i >> 6)) * CV_S + 1 + (i & 63)] = cvq[i];
    if (t < 68) { s_cv[t] = 0.f; s_cv[65 * CV_S + t] = 0.f; }
    if (t < 64) {
        s_cv[(t + 1) * CV_S] = 0.f;
        s_cv[(t + 1) * CV_S + 65] = 0.f;
        s_cv[(t + 1) * CV_S + 66] = 0.f;
    }
    for (int i = t; i < 160; i += 256) {
        float* rb = &s_occ[i * OC_S];
        rb[0] = 0.f; rb[65] = 0.f; rb[66] = 0.f; rb[67] = 0.f;
    }
    for (int i = t; i < 144; i += 256) { int c = i / 9, k = i - c * 9; s_w2[c * 12 + k] = w2[i]; }
    for (int i = t; i < 72 * 32; i += 256) {
        int krow = i >> 5, oc = i & 31;
        int k = krow * 2;
        s_w3b[krow * 36 + (oc & 7) * 4 + (oc >> 3)] = packbf(w3[oc * 144 + k], w3[oc * 144 + k + 1]);
    }
    for (int i = t; i < 144; i += 256) {
        int ic = i / 9, rk = i - ic * 9;
        int dy = rk / 3, dx = rk - dy * 3;
        s_koi[i] = (dy * 16 + ic) * OC_S + dx;
    }
    for (int i = t; i < 512; i += 256) s_w4[i] = w4[i];
    if (t < 32) s_b3[t] = b3[t];
    if (t < 16) s_b4[t] = b4[t];
    if (t < 32) s_ow[t] = occw[t];
    if (t < 2)  s_ob[t] = occb[t];
    if (t < 32) s_o3[t] = 0.f;
    for (int i = t; i < 128; i += 256) g_feats[q * 384 + i] = hq[q * 128 + i];
    for (int i = t; i < 256; i += 256) g_feats[q * 384 + 128 + i] = qf[q * 256 + i];
    float b2v = b2[0];

    int c1 = t & 15, xg = (t >> 4) & 7, sl2 = t >> 7;
    int x0 = xg * 8;
    float w1r[9], b1r = b1[c1];
#pragma unroll
    for (int k = 0; k < 9; k++) w1r[k] = w1[c1 * 9 + k];

    int rr2 = (t >> 4) & 7, cg2 = t & 15;
    bool c2act = (t < 128);
    float pm[32];

    int wrp = t >> 5, lane = t & 31, qd = lane & 3, g = lane >> 2;
    int jrow3 = wrp >> 1;
    int col0 = (wrp & 1) * 16 + g;
    int base0 = (2 * jrow3 + 1) * (16 * OC_S) + 2 * col0 + 1;
    float macc[4][2];
#pragma unroll
    for (int nt = 0; nt < 4; nt++) { macc[nt][0] = 0.f; macc[nt][1] = 0.f; }

    __syncthreads();

    float b3n[4][2];
#pragma unroll
    for (int nt = 0; nt < 4; nt++) {
        b3n[nt][0] = s_b3[nt * 8 + qd * 2 + 0];
        b3n[nt][1] = s_b3[nt * 8 + qd * 2 + 1];
    }

    for (int r0 = 0; r0 < 64; r0 += 8) {
        int band = r0 >> 3;
#pragma unroll
        for (int s = 0; s < 5; s++) {
            int slot = sl2 + 2 * s;
            int row = r0 - 1 + slot;
            float* dst = &s_occ[(slot * 16 + c1) * OC_S + 1 + x0];
            if (row < 0 || row > 63) {
#pragma unroll
                for (int j = 0; j < 8; j++) dst[j] = 0.f;
                continue;
            }
            float xv[3][10];
#pragma unroll
            for (int dy = 0; dy < 3; dy++) {
                const float* rp = &s_cv[(row + dy) * CV_S + x0];
                float4 vA = *(const float4*)rp;
                float4 vB = *(const float4*)(rp + 4);
                float2 vC = *(const float2*)(rp + 8);
                xv[dy][0] = vA.x; xv[dy][1] = vA.y; xv[dy][2] = vA.z; xv[dy][3] = vA.w;
                xv[dy][4] = vB.x; xv[dy][5] = vB.y; xv[dy][6] = vB.z; xv[dy][7] = vB.w;
                xv[dy][8] = vC.x; xv[dy][9] = vC.y;
            }
#pragma unroll
            for (int j = 0; j < 8; j++) {
                float a = b1r;
#pragma unroll
                for (int dy = 0; dy < 3; dy++)
#pragma unroll
                    for (int dx = 0; dx < 3; dx++)
                        a = fmaf(w1r[dy * 3 + dx], xv[dy][j + dx], a);
                dst[j] = fmaxf(a, 0.f);
            }
        }
        __syncthreads();

        if (c2act) {
            float a[4] = {b2v, b2v, b2v, b2v};
#pragma unroll
            for (int c = 0; c < 16; c++) {
                float4 wA = *(const float4*)&s_w2[c * 12];
                float4 wB = *(const float4*)&s_w2[c * 12 + 4];
                float w8 = s_w2[c * 12 + 8];
                float wv[9] = {wA.x, wA.y, wA.z, wA.w, wB.x, wB.y, wB.z, wB.w, w8};
#pragma unroll
                for (int dy = 0; dy < 3; dy++) {
                    const float* rp = &s_occ[((rr2 + dy) * 16 + c) * OC_S + 4 * cg2];
                    float4 vA = *(const float4*)rp;
                    float2 vB = *(const float2*)(rp + 4);
                    float v[6] = {vA.x, vA.y, vA.z, vA.w, vB.x, vB.y};
#pragma unroll
                    for (int j = 0; j < 4; j++)
                        a[j] = fmaf(wv[dy * 3 + 0], v[j],
                               fmaf(wv[dy * 3 + 1], v[j + 1],
                               fmaf(wv[dy * 3 + 2], v[j + 2], a[j])));
                }
            }
#pragma unroll
            for (int j = 0; j < 4; j++) pm[band * 4 + j] = a[j];
        }

        {
            float d[4][4];
#pragma unroll
            for (int nt = 0; nt < 4; nt++)
#pragma unroll
                for (int u = 0; u < 4; u++) d[nt][u] = 0.f;

#pragma unroll
            for (int st = 0; st < 9; st++) {
                int kE = st * 16 + 2 * qd;
                int kO = kE + 8;
                int e0 = s_koi[kE], e1 = s_koi[kE + 1];
                int o0 = s_koi[kO], o1 = s_koi[kO + 1];
                unsigned a0 = packbf(s_occ[base0 + e0],      s_occ[base0 + e1]);
                unsigned a1 = packbf(s_occ[base0 + 16 + e0], s_occ[base0 + 16 + e1]);
                unsigned a2 = packbf(s_occ[base0 + o0],      s_occ[base0 + o1]);
                unsigned a3 = packbf(s_occ[base0 + 16 + o0], s_occ[base0 + 16 + o1]);
                int kr = st * 8 + qd;
                uint4 bw0 = *(const uint4*)&s_w3b[kr * 36 + g * 4];
                uint4 bw1 = *(const uint4*)&s_w3b[(kr + 4) * 36 + g * 4];
                mma_bf16(d[0][0], d[0][1], d[0][2], d[0][3], a0, a1, a2, a3, bw0.x, bw1.x);
                mma_bf16(d[1][0], d[1][1], d[1][2], d[1][3], a0, a1, a2, a3, bw0.y, bw1.y);
                mma_bf16(d[2][0], d[2][1], d[2][2], d[2][3], a0, a1, a2, a3, bw0.z, bw1.z);
                mma_bf16(d[3][0], d[3][1], d[3][2], d[3][3], a0, a1, a2, a3, bw0.w, bw1.w);
            }
#pragma unroll
            for (int nt = 0; nt < 4; nt++) {
                macc[nt][0] += fmaxf(d[nt][0] + b3n[nt][0], 0.f) + fmaxf(d[nt][2] + b3n[nt][0], 0.f);
                macc[nt][1] += fmaxf(d[nt][1] + b3n[nt][1], 0.f) + fmaxf(d[nt][3] + b3n[nt][1], 0.f);
            }
        }
        __syncthreads();
    }

#pragma unroll
    for (int nt = 0; nt < 4; nt++) {
#pragma unroll
        for (int j = 0; j < 2; j++) {
            float v = macc[nt][j];
#pragma unroll
            for (int o = 4; o <= 16; o <<= 1) v += __shfl_xor_sync(0xffffffffu, v, o);
            if (g == 0) atomicAdd(&s_o3[nt * 8 + qd * 2 + j], v);
        }
    }

    float lmax = -1e30f;
    if (c2act) {
#pragma unroll
        for (int u = 0; u < 32; u++) lmax = fmaxf(lmax, pm[u]);
    }
#pragma unroll
    for (int o = 16; o; o >>= 1) lmax = fmaxf(lmax, __shfl_xor_sync(0xffffffffu, lmax, o));
    if ((t & 31) == 0) s_red[t >> 5] = lmax;
    __syncthreads();
    if (t == 0) {
        float m = s_red[0];
        for (int i = 1; i < 8; i++) m = fmaxf(m, s_red[i]);
        s_red[31] = m;
    }
    __syncthreads();
    float m = s_red[31];
    float se = 0.f, sy = 0.f, sx = 0.f;
    if (c2act) {
#pragma unroll
        for (int b = 0; b < 8; b++) {
            float rowf = (float)(8 * b + rr2);
#pragma unroll
            for (int j = 0; j < 4; j++) {
                float e = __expf((pm[b * 4 + j] - m) * 20.f);
                se += e;
                sy = fmaf(e, rowf, sy);
                sx = fmaf(e, (float)(4 * cg2 + j), sx);
            }
        }
    }
    __syncthreads();
#pragma unroll
    for (int o = 16; o; o >>= 1) {
        se += __shfl_xor_sync(0xffffffffu, se, o);
        sy += __shfl_xor_sync(0xffffffffu, sy, o);
        sx += __shfl_xor_sync(0xffffffffu, sx, o);
    }
    if ((t & 31) == 0) { int w = t >> 5; s_red[w] = se; s_red[8 + w] = sy; s_red[16 + w] = sx; }
    __syncthreads();
    if (t == 0) {
        float Se = 0, Sy = 0, Sx = 0;
        for (int i = 0; i < 8; i++) { Se += s_red[i]; Sy += s_red[8 + i]; Sx += s_red[16 + i]; }
        g_pos[q * 2 + 0] = (Sx / Se) * 8.f;
        g_pos[q * 2 + 1] = (Sy / Se) * 8.f;
    }
    __syncthreads();

    if (t < 16) {
        float a = s_b4[t];
        for (int ic = 0; ic < 32; ic++) a = fmaf(s_o3[ic] * (1.f / 1024.f), s_w4[ic * 16 + t], a);
        s_h4[t] = fmaxf(a, 0.f);
    }
    __syncthreads();
    if (t == 0) {
        float o = s_ob[0], ex2 = s_ob[1];
        for (int k = 0; k < 16; k++) {
            o   = fmaf(s_h4[k], s_ow[k * 2 + 0], o);
            ex2 = fmaf(s_h4[k], s_ow[k * 2 + 1], ex2);
        }
        g_occv[q] = o;
        g_expd[q] = ex2;
    }
}

// ---------------- correlation (fp32 grids, ILP-4, verified) ----------------
__global__ __launch_bounds__(256) void k_corr(const float* __restrict__ hg,
                                              const float* __restrict__ fg) {
    __shared__ float s_q[384];
    __shared__ float s_D[64];
    int q = blockIdx.x, t = threadIdx.x;
    float px = g_pos[q * 2 + 0], py = g_pos[q * 2 + 1];
    for (int i = t; i < 384; i += 256) s_q[i] = g_feats[q * 384 + i];
    __nv_bfloat16* mih = g_mlpinh + q * MI_STRIDE;
    if (t == 0) {
        mih[0] = __float2bfloat16(0.f);
        mih[1] = __float2bfloat16(0.f);
        mih[2] = __float2bfloat16(g_occv[q]);
        mih[3] = __float2bfloat16(g_expd[q]);
    }
    if (t >= 215 && t < 256) mih[535 + (t - 215)] = __float2bfloat16(0.f);   // pad 535..575
    for (int i = t; i < 384; i += 256) mih[4 + i] = __float2bfloat16(g_feats[q * 384 + i]);
    __syncthreads();

    const float* Gs[3] = { hg, fg, g_fgavg };
    const int Hs[3] = { 128, 64, 32 };
    const int Cs[3] = { 128, 256, 256 };
    const int QO[3] = { 0, 128, 128 };

    int wrp = t >> 5, lane = t & 31;
#pragma unroll
    for (int l = 0; l < 3; l++) {
        const float* G = Gs[l];
        const int H = Hs[l], C = Cs[l], qo = QO[l];
        float sc = (float)H / 512.f;
        float gy = py * sc, gx = px * sc;
        float y0f = floorf(gy), x0f = floorf(gx);
        float wy = gy - y0f, wx = gx - x0f;
        int y0 = (int)y0f, x0 = (int)x0f;
        const float* sq = s_q + qo;

#pragma unroll
        for (int pp = 0; pp < 8; pp++) {
            int p = wrp + pp * 8;
            int ry = min(max(y0 + (p >> 3) - 3, 0), H - 1);
            int rx = min(max(x0 + (p & 7) - 3, 0), H - 1);
            const float* gp = G + (ry * H + rx) * C;
            float s0 = gp[lane] * sq[lane];
            float s1 = gp[lane + 32] * sq[lane + 32];
            float s2 = gp[lane + 64] * sq[lane + 64];
            float s3 = gp[lane + 96] * sq[lane + 96];
            if (C == 256) {
                s0 = fmaf(gp[lane + 128], sq[lane + 128], s0);
                s1 = fmaf(gp[lane + 160], sq[lane + 160], s1);
                s2 = fmaf(gp[lane + 192], sq[lane + 192], s2);
                s3 = fmaf(gp[lane + 224], sq[lane + 224], s3);
            }
            float s = (s0 + s1) + (s2 + s3);
#pragma unroll
            for (int o = 16; o; o >>= 1) s += __shfl_xor_sync(0xffffffffu, s, o);
            if (lane == 0) s_D[p] = s;
        }
        __syncthreads();
        if (t < 49) {
            int r = t / 7, c2 = t - r * 7;
            float d00 = s_D[r * 8 + c2],       d01 = s_D[r * 8 + c2 + 1];
            float d10 = s_D[(r + 1) * 8 + c2], d11 = s_D[(r + 1) * 8 + c2 + 1];
            float corr = (1.f - wy) * (1.f - wx) * d00 + (1.f - wy) * wx * d01
                       + wy * (1.f - wx) * d10 + wy * wx * d11;
            mih[388 + l * 49 + t] = __float2bfloat16(corr);
        }
        __syncthreads();
    }
}

// ---------------- GEMM1: 32M x 64N tiles, K-step 64, 9 stages ----------------
#define KS 72
__global__ __launch_bounds__(256) void k_gemm1(const float* __restrict__ bias) {
    __shared__ __align__(16) __nv_bfloat16 As[2][32 * KS];
    __shared__ __align__(16) __nv_bfloat16 Bs[2][64 * KS];
    int n0 = blockIdx.x * 64, m0 = blockIdx.y * 32, t = threadIdx.x;
    int w = t >> 5, lane = t & 31, qd = lane & 3, g = lane >> 2;
    int wm = (w & 1) * 16, wn = (w >> 1) * 16;
    int fr = t >> 3, fc = (t & 7) * 8;   // A: row 0..31, col group; B: rows fr, fr+32
    float acc[2][4];
#pragma unroll
    for (int nt = 0; nt < 2; nt++)
#pragma unroll
        for (int u = 0; u < 4; u++) acc[nt][u] = 0.f;

    const int NS = 9;   // 576 / 64
    *(uint4*)&As[0][fr * KS + fc] = *(const uint4*)&g_mlpinh[(m0 + fr) * MI_STRIDE + fc];
    *(uint4*)&Bs[0][fr * KS + fc] = *(const uint4*)&g_miwh[(n0 + fr) * 576 + fc];
    *(uint4*)&Bs[0][(fr + 32) * KS + fc] = *(const uint4*)&g_miwh[(n0 + fr + 32) * 576 + fc];
    __syncthreads();

    for (int st = 0; st < NS; st++) {
        int cur = st & 1;
        if (st + 1 < NS) {
            int nb = (st + 1) & 1, k0 = (st + 1) * 64;
            *(uint4*)&As[nb][fr * KS + fc] = *(const uint4*)&g_mlpinh[(m0 + fr) * MI_STRIDE + k0 + fc];
            *(uint4*)&Bs[nb][fr * KS + fc] = *(const uint4*)&g_miwh[(n0 + fr) * 576 + k0 + fc];
            *(uint4*)&Bs[nb][(fr + 32) * KS + fc] = *(const uint4*)&g_miwh[(n0 + fr + 32) * 576 + k0 + fc];
        }
#pragma unroll
        for (int s = 0; s < 4; s++) {
            unsigned a[4], b[2][2];
            int row = wm + g;
            a[0] = *(const unsigned*)&As[cur][row * KS + s * 16 + 2 * qd];
            a[1] = *(const unsigned*)&As[cur][(row + 8) * KS + s * 16 + 2 * qd];
            a[2] = *(const unsigned*)&As[cur][row * KS + s * 16 + 2 * qd + 8];
            a[3] = *(const unsigned*)&As[cur][(row + 8) * KS + s * 16 + 2 * qd + 8];
#pragma unroll
            for (int nt = 0; nt < 2; nt++) {
                int bn = wn + nt * 8 + g;
                b[nt][0] = *(const unsigned*)&Bs[cur][bn * KS + s * 16 + 2 * qd];
                b[nt][1] = *(const unsigned*)&Bs[cur][bn * KS + s * 16 + 2 * qd + 8];
            }
#pragma unroll
            for (int nt = 0; nt < 2; nt++)
                mma_bf16(acc[nt][0], acc[nt][1], acc[nt][2], acc[nt][3],
                         a[0], a[1], a[2], a[3], b[nt][0], b[nt][1]);
        }
        __syncthreads();
    }
#pragma unroll
    for (int nt = 0; nt < 2; nt++) {
        int mg = m0 + wm + g;
        int ng = n0 + wn + nt * 8 + qd * 2;
        float bz0 = bias[ng], bz1 = bias[ng + 1];
        unsigned h0 = packbf(gelu_tanh(acc[nt][0] + bz0), gelu_tanh(acc[nt][1] + bz1));
        unsigned h1 = packbf(gelu_tanh(acc[nt][2] + bz0), gelu_tanh(acc[nt][3] + bz1));
        *(unsigned*)&g_hidh[mg * 512 + ng] = h0;
        *(unsigned*)&g_hidh[(mg + 8) * 512 + ng] = h1;
    }
}

// ---------------- GEMM2: 32M x 64N tiles, K-step 64, 8 stages (last=1: output) ----------------
__global__ __launch_bounds__(256) void k_gemm2(const float* __restrict__ bias,
                                               float* __restrict__ out, int last) {
    __shared__ __align__(16) __nv_bfloat16 As[2][32 * KS];
    __shared__ __align__(16) __nv_bfloat16 Bs[2][64 * KS];
    int n0 = blockIdx.x * 64, m0 = blockIdx.y * 32, t = threadIdx.x;
    int w = t >> 5, lane = t & 31, qd = lane & 3, g = lane >> 2;
    int wm = (w & 1) * 16, wn = (w >> 1) * 16;
    int fr = t >> 3, fc = (t & 7) * 8;
    float acc[2][4];
#pragma unroll
    for (int nt = 0; nt < 2; nt++)
#pragma unroll
        for (int u = 0; u < 4; u++) acc[nt][u] = 0.f;

    const int NS = 8;   // 512 / 64
    *(uint4*)&As[0][fr * KS + fc] = *(const uint4*)&g_hidh[(m0 + fr) * 512 + fc];
    *(uint4*)&Bs[0][fr * KS + fc] = *(const uint4*)&g_mowh[(n0 + fr) * 512 + fc];
    *(uint4*)&Bs[0][(fr + 32) * KS + fc] = *(const uint4*)&g_mowh[(n0 + fr + 32) * 512 + fc];
    __syncthreads();

    for (int st = 0; st < NS; st++) {
        int cur = st & 1;
        if (st + 1 < NS) {
            int nb = (st + 1) & 1, k0 = (st + 1) * 64;
            *(uint4*)&As[nb][fr * KS + fc] = *(const uint4*)&g_hidh[(m0 + fr) * 512 + k0 + fc];
            *(uint4*)&Bs[nb][fr * KS + fc] = *(const uint4*)&g_mowh[(n0 + fr) * 512 + k0 + fc];
            *(uint4*)&Bs[nb][(fr + 32) * KS + fc] = *(const uint4*)&g_mowh[(n0 + fr + 32) * 512 + k0 + fc];
        }
#pragma unroll
        for (int s = 0; s < 4; s++) {
            unsigned a[4], b[2][2];
            int row = wm + g;
            a[0] = *(const unsigned*)&As[cur][row * KS + s * 16 + 2 * qd];
            a[1] = *(const unsigned*)&As[cur][(row + 8) * KS + s * 16 + 2 * qd];
            a[2] = *(const unsigned*)&As[cur][row * KS + s * 16 + 2 * qd + 8];
            a[3] = *(const unsigned*)&As[cur][(row + 8) * KS + s * 16 + 2 * qd + 8];
#pragma unroll
            for (int nt = 0; nt < 2; nt++) {
                int bn = wn + nt * 8 + g;
                b[nt][0] = *(const unsigned*)&Bs[cur][bn * KS + s * 16 + 2 * qd];
                b[nt][1] = *(const unsigned*)&Bs[cur][bn * KS + s * 16 + 2 * qd + 8];
            }
#pragma unroll
            for (int nt = 0; nt < 2; nt++)
                mma_bf16(acc[nt][0], acc[nt][1], acc[nt][2], acc[nt][3],
                         a[0], a[1], a[2], a[3], b[nt][0], b[nt][1]);
        }
        __syncthreads();
    }
#pragma unroll
    for (int nt = 0; nt < 2; nt++) {
#pragma unroll
        for (int rr = 0; rr < 2; rr++) {
            int mg = m0 + wm + g + rr * 8;
#pragma unroll
            for (int jj = 0; jj < 2; jj++) {
                int ng = n0 + wn + nt * 8 + qd * 2 + jj;
                if (ng < 388) {
                    float v = acc[nt][rr * 2 + jj] + bias[ng];
                    if (ng < 2) {
                        float nv = g_pos[mg * 2 + ng] + v;
                        g_pos[mg * 2 + ng] = nv;
                        if (last) out[mg * 4 + ng] = nv;
                    } else if (ng == 2) {
                        float nv = g_occv[mg] + v;
                        g_occv[mg] = nv;
                        if (last) out[mg * 4 + 2] = nv;
                    } else if (ng == 3) {
                        float nv = g_expd[mg] + v;
                        g_expd[mg] = nv;
                        if (last) out[mg * 4 + 3] = nv;
                    } else {
                        g_feats[mg * 384 + ng - 4] += v;
                    }
                }
            }
        }
    }
}

// ---------------- launch ----------------
extern "C" void kernel_launch(void* const* d_in, const int* in_sizes, int n_in,
                              void* d_out, int out_size) {
    const float* fg   = (const float*)d_in[0];
    const float* hg   = (const float*)d_in[1];
    const float* qf   = (const float*)d_in[2];
    const float* hq   = (const float*)d_in[3];
    const float* w1   = (const float*)d_in[4];
    const float* b1   = (const float*)d_in[5];
    const float* w2   = (const float*)d_in[6];
    const float* b2   = (const float*)d_in[7];
    const float* w3   = (const float*)d_in[8];
    const float* b3   = (const float*)d_in[9];
    const float* w4   = (const float*)d_in[10];
    const float* b4   = (const float*)d_in[11];
    const float* occw = (const float*)d_in[12];
    const float* occb = (const float*)d_in[13];
    const float* miw  = (const float*)d_in[14];
    const float* mib  = (const float*)d_in[15];
    const float* mow  = (const float*)d_in[16];
    const float* mob  = (const float*)d_in[17];
    float* out = (float*)d_out;

    const int smem_head = 18970 * 4;
    cudaFuncSetAttribute(k_head, cudaFuncAttributeMaxDynamicSharedMemorySize, smem_head);

    k_cv<<<dim3(64, 16), 256>>>(qf, fg, g_cv);
    k_fgavg<<<1024, 256>>>(fg, g_fgavg);
    k_prep<<<960, 256>>>(miw, mow);
    k_head<<<NQ, 256, smem_head>>>(g_cv, hq, qf, w1, b1, w2, b2, w3, b3, w4, b4, occw, occb);

    for (int it = 0; it < 4; it++) {
        k_corr<<<NQ, 256>>>(hg, fg);
        k_gemm1<<<dim3(8, 32), 256>>>(mib);
        k_gemm2<<<dim3(7, 32), 256>>>(mob, out, it == 3 ? 1 : 0);
    }
}